// round 3
// baseline (speedup 1.0000x reference)
#include <cuda_runtime.h>
#include <cstdint>

// ============================================================================
// MTSCNN: 64 per-channel conv extractors + (folded) linear tail. Scalar-FFMA
// variant (no f32x2 packed math) to de-risk the repeated container failures.
//
// Algebra exploited:
//  * No activation after `feat` -> per-channel FC (32->64->32->1) and the
//    detection head (64->64->1) compose into one [64x32] weight W plus a
//    scalar C0:   out[b] = sum_{c,f} feat[b,c,f] * W[c,f] + C0
//  * maxpool trims conv2's 5th position -> l=4 dead -> p1[*][6], t[14..15] dead.
//
// One thread = (channel c, batch pair): two samples per thread so each weight
// load feeds 2 FMAs. Weights repacked channel-last so a warp (lanes = channels)
// hits one 128B line per weight scalar.
// ============================================================================

__device__ __forceinline__ float leaky(float x) { return fmaxf(x, 0.05f * x); }

// ---- precomputed / repacked parameter storage (channel-last) ----
__device__ float g_w1t[24 * 64];   // [(o*3+k)*64 + c]
__device__ float g_b1t[8 * 64];    // [o*64 + c]
__device__ float g_w2t[384 * 64];  // [((o2*8+o)*3+k)*64 + c]
__device__ float g_b2t[16 * 64];   // [o2*64 + c]
__device__ float g_Wt[32 * 64];    // [f*64 + c]  (folded linear tail)
__device__ float g_r2[64 * 64];    // scratch: fw3_c @ fw2_c   [c*64 + j]
__device__ float g_u[64];          // dw2 @ dw1
__device__ float g_C0[1];

// ============================================================================
// pre1: repack conv weights channel-last; compute r2[c][j] and u[c].
// ============================================================================
__global__ void mtscnn_pre1(const float* __restrict__ w1, const float* __restrict__ b1,
                            const float* __restrict__ w2, const float* __restrict__ b2,
                            const float* __restrict__ fw2, const float* __restrict__ fw3,
                            const float* __restrict__ dw1, const float* __restrict__ dw2) {
    int tid = blockIdx.x * blockDim.x + threadIdx.x;
    if (tid < 4096) {
        int c = tid >> 6, j = tid & 63;
        float s = 0.f;
#pragma unroll
        for (int i = 0; i < 32; i++)
            s += fw3[c * 32 + i] * fw2[c * 2048 + i * 64 + j];
        g_r2[c * 64 + j] = s;
    } else if (tid < 4160) {
        int c = tid - 4096;
        float s = 0.f;
#pragma unroll
        for (int j = 0; j < 64; j++) s += dw2[j] * dw1[j * 64 + c];
        g_u[c] = s;
    } else if (tid < 4160 + 1536) {
        int i = tid - 4160;            // i = c*24 + (o*3+k)
        int c = i / 24, r = i % 24;
        g_w1t[r * 64 + c] = w1[i];
    } else if (tid < 4160 + 1536 + 512) {
        int i = tid - (4160 + 1536);   // i = c*8 + o
        int c = i >> 3, o = i & 7;
        g_b1t[o * 64 + c] = b1[i];
    } else if (tid < 4160 + 1536 + 512 + 24576) {
        int i = tid - (4160 + 1536 + 512);  // i = c*384 + (o2*24 + o*3 + k)
        int c = i / 384, r = i % 384;
        g_w2t[r * 64 + c] = w2[i];
    } else if (tid < 4160 + 1536 + 512 + 24576 + 1024) {
        int i = tid - (4160 + 1536 + 512 + 24576);  // i = c*16 + o2
        int c = i >> 4, o2 = i & 15;
        g_b2t[o2 * 64 + c] = b2[i];
    }
}

// ============================================================================
// pre2: fold the linear tail.
//   W[c][f] = u[c] * sum_j r2[c][j] * fw1[c][j][f]
//   C0      = sum_c u[c]*b_eff[c] + dw2.db1 + db2
//   b_eff[c] = sum_j r2[c][j]*fb1[c][j] + sum_i fw3[c][i]*fb2[c][i] + fb3[c]
// ============================================================================
__global__ void mtscnn_pre2(const float* __restrict__ fw1, const float* __restrict__ fb1,
                            const float* __restrict__ fb2, const float* __restrict__ fb3,
                            const float* __restrict__ fw3,
                            const float* __restrict__ db1, const float* __restrict__ dw2,
                            const float* __restrict__ db2) {
    __shared__ float sh_beff[64];
    int tid = threadIdx.x;
    for (int e = tid; e < 2048; e += blockDim.x) {
        int c = e >> 5, f = e & 31;
        float s = 0.f;
#pragma unroll
        for (int j = 0; j < 64; j++)
            s += g_r2[c * 64 + j] * fw1[c * 2048 + j * 32 + f];
        g_Wt[f * 64 + c] = g_u[c] * s;
    }
    if (tid < 64) {
        int c = tid;
        float s = 0.f;
#pragma unroll
        for (int j = 0; j < 64; j++) s += g_r2[c * 64 + j] * fb1[c * 64 + j];
#pragma unroll
        for (int i = 0; i < 32; i++) s += fw3[c * 32 + i] * fb2[c * 32 + i];
        sh_beff[c] = s + fb3[c];
    }
    __syncthreads();
    if (tid == 0) {
        float C = db2[0];
        for (int j = 0; j < 64; j++) C += dw2[j] * db1[j];
        for (int c = 0; c < 64; c++) C += g_u[c] * sh_beff[c];
        g_C0[0] = C;
    }
}

// ============================================================================
// main: thread = (channel c, batch pair). lo = sample 2p, hi = sample 2p+1.
// Block = 128 threads = 2 pairs x 64 channels -> 4 samples per block.
// ============================================================================
__global__ __launch_bounds__(128, 2) void mtscnn_main(const float* __restrict__ x,
                                                      float* __restrict__ out) {
    const int c  = threadIdx.x & 63;
    const int pl = threadIdx.x >> 6;                      // which pair in block
    const long long pairIdx = (long long)blockIdx.x * 2 + pl;
    const size_t base = (size_t)pairIdx * 2048 + c;       // 1024 floats per sample

    // ---- load input taps (t[14..15] dead after pool-trim analysis) ----
    float tl[14], th[14];
#pragma unroll
    for (int i = 0; i < 14; i++) {
        tl[i] = x[base + i * 64];
        th[i] = x[base + 1024 + i * 64];
    }

    // ---- conv1 (K=3, valid) + leaky + maxpool2: pooled outputs 0..5 only ----
    float p1l[8][6], p1h[8][6];
#pragma unroll
    for (int o = 0; o < 8; o++) {
        float w0 = g_w1t[(o * 3 + 0) * 64 + c];
        float w1 = g_w1t[(o * 3 + 1) * 64 + c];
        float w2 = g_w1t[(o * 3 + 2) * 64 + c];
        float bb = g_b1t[o * 64 + c];
#pragma unroll
        for (int j = 0; j < 6; j++) {
            float aL = fmaf(w0, tl[2 * j],     fmaf(w1, tl[2 * j + 1], fmaf(w2, tl[2 * j + 2], bb)));
            float bL = fmaf(w0, tl[2 * j + 1], fmaf(w1, tl[2 * j + 2], fmaf(w2, tl[2 * j + 3], bb)));
            float aH = fmaf(w0, th[2 * j],     fmaf(w1, th[2 * j + 1], fmaf(w2, th[2 * j + 2], bb)));
            float bH = fmaf(w0, th[2 * j + 1], fmaf(w1, th[2 * j + 2], fmaf(w2, th[2 * j + 3], bb)));
            p1l[o][j] = fmaxf(leaky(aL), leaky(bL));
            p1h[o][j] = fmaxf(leaky(aH), leaky(bH));
        }
    }

    // ---- conv2 (8->16, K=3) + leaky + maxpool2 (l=4 dead) + folded-tail dot ----
    float slo = 0.f, shi = 0.f;
#pragma unroll 1
    for (int o2 = 0; o2 < 16; o2++) {
        float bb = g_b2t[o2 * 64 + c];
        float a0l = bb, a1l = bb, a2l = bb, a3l = bb;
        float a0h = bb, a1h = bb, a2h = bb, a3h = bb;
#pragma unroll
        for (int o = 0; o < 8; o++) {
#pragma unroll
            for (int k = 0; k < 3; k++) {
                float w = g_w2t[((o2 * 8 + o) * 3 + k) * 64 + c];
                a0l = fmaf(w, p1l[o][k],     a0l);
                a1l = fmaf(w, p1l[o][k + 1], a1l);
                a2l = fmaf(w, p1l[o][k + 2], a2l);
                a3l = fmaf(w, p1l[o][k + 3], a3l);
                a0h = fmaf(w, p1h[o][k],     a0h);
                a1h = fmaf(w, p1h[o][k + 1], a1h);
                a2h = fmaf(w, p1h[o][k + 2], a2h);
                a3h = fmaf(w, p1h[o][k + 3], a3h);
            }
        }
        float q0l = fmaxf(leaky(a0l), leaky(a1l));
        float q1l = fmaxf(leaky(a2l), leaky(a3l));
        float q0h = fmaxf(leaky(a0h), leaky(a1h));
        float q1h = fmaxf(leaky(a2h), leaky(a3h));
        float Wf0 = g_Wt[(o2 * 2 + 0) * 64 + c];
        float Wf1 = g_Wt[(o2 * 2 + 1) * 64 + c];
        slo = fmaf(q0l, Wf0, fmaf(q1l, Wf1, slo));
        shi = fmaf(q0h, Wf0, fmaf(q1h, Wf1, shi));
    }

    // ---- reduce over the 64 channels (2 warps per pair) ----
#pragma unroll
    for (int off = 16; off > 0; off >>= 1) {
        slo += __shfl_down_sync(0xffffffffu, slo, off);
        shi += __shfl_down_sync(0xffffffffu, shi, off);
    }
    __shared__ float red[4][2];
    int w = threadIdx.x >> 5;
    if ((threadIdx.x & 31) == 0) {
        red[w][0] = slo;
        red[w][1] = shi;
    }
    __syncthreads();
    if ((threadIdx.x & 63) == 0) {
        float C0 = g_C0[0];
        long long b0 = pairIdx * 2;
        out[b0]     = red[pl * 2][0] + red[pl * 2 + 1][0] + C0;
        out[b0 + 1] = red[pl * 2][1] + red[pl * 2 + 1][1] + C0;
    }
}

// ============================================================================
// launch
// ============================================================================
extern "C" void kernel_launch(void* const* d_in, const int* in_sizes, int n_in,
                              void* d_out, int out_size) {
    const float* x   = (const float*)d_in[0];
    const float* w1  = (const float*)d_in[1];
    const float* b1  = (const float*)d_in[2];
    const float* w2  = (const float*)d_in[3];
    const float* b2  = (const float*)d_in[4];
    const float* fw1 = (const float*)d_in[5];
    const float* fb1 = (const float*)d_in[6];
    const float* fw2 = (const float*)d_in[7];
    const float* fb2 = (const float*)d_in[8];
    const float* fw3 = (const float*)d_in[9];
    const float* fb3 = (const float*)d_in[10];
    const float* dw1 = (const float*)d_in[11];
    const float* db1 = (const float*)d_in[12];
    const float* dw2 = (const float*)d_in[13];
    const float* db2 = (const float*)d_in[14];
    float* out = (float*)d_out;

    mtscnn_pre1<<<125, 256>>>(w1, b1, w2, b2, fw2, fw3, dw1, dw2);
    mtscnn_pre2<<<1, 1024>>>(fw1, fb1, fb2, fb3, fw3, db1, dw2, db2);

    int B = in_sizes[0] / 1024;          // 32768 (x is [B,1,16,8,8])
    int nPairs = B / 2;                  // 2 samples per thread
    int nBlocks = nPairs / 2;            // 2 pairs per 128-thread block
    mtscnn_main<<<nBlocks, 128>>>(x, out);
}